// round 13
// baseline (speedup 1.0000x reference)
#include <cuda_runtime.h>
#include <cuda_bf16.h>
#include <cuda_fp16.h>
#include <cstdint>

#define NGT 512
#define NSP 200
#define NED 397
#define DD  64
#define NN  399
#define EPT 398
#define ECOLS (NGT*EPT*2)
#define RS  65
#define HS  72                 /* fp16 row stride (conflict-free ldmatrix) */
#define GTS (NGT*DD)
#define KPAD 208               /* 13 k-steps of 16 (>= 200 species) */
#define KQ4  26                /* KPAD/8: uint4 chunks per row */
#define EPAD 512

/* gin smem layout (bytes) */
#define GIN_HOFF 113456
#define GIN_WOFF 171056
#define GIN_SMEM 180272

typedef unsigned char u8;
typedef unsigned long long ull;
typedef unsigned int u32;
typedef unsigned short u16;

/* ---------------- scratch (static device globals) ----------------------- */
__device__ __nv_bfloat16 g_pool_bf[(size_t)NSP*NGT*DD];   /* [s][g][d] 13MB */
__device__ __nv_bfloat16 g_poolT[(size_t)GTS*KPAD];       /* [gd][s] */
__device__ __nv_bfloat16 g_validT[(size_t)NGT*KPAD];      /* [g][s] */
__device__ __nv_bfloat16 g_maskA[(size_t)EPAD*KPAD];      /* [e][s] */
__device__ float g_valid[NSP*NGT];                        /* [s][g] */
__device__ float g_gt[(size_t)400*GTS];                   /* [e][g][d] 52MB */
__device__ float g_minv[(size_t)EPAD*NGT];                /* [e][g] */

__device__ __forceinline__ u32 smem_u32(const void* p){
    u32 a; asm("{ .reg .u64 t; cvta.to.shared.u64 t, %1; cvt.u32.u64 %0, t; }" : "=r"(a) : "l"(p));
    return a;
}
#define LDSM_X4(r0,r1,r2,r3,addr) \
    asm volatile("ldmatrix.sync.aligned.m8n8.x4.shared.b16 {%0,%1,%2,%3}, [%4];" \
        : "=r"(r0), "=r"(r1), "=r"(r2), "=r"(r3) : "r"(addr))
#define LDSM_X4_T(r0,r1,r2,r3,addr) \
    asm volatile("ldmatrix.sync.aligned.m8n8.x4.trans.shared.b16 {%0,%1,%2,%3}, [%4];" \
        : "=r"(r0), "=r"(r1), "=r"(r2), "=r"(r3) : "r"(addr))
#define MMA_BF16(c0,c1,c2,c3,a0,a1,a2,a3,b0,b1) \
    asm volatile("mma.sync.aligned.m16n8k16.row.col.f32.bf16.bf16.f32 " \
        "{%0,%1,%2,%3},{%4,%5,%6,%7},{%8,%9},{%0,%1,%2,%3};" \
        : "+f"(c0), "+f"(c1), "+f"(c2), "+f"(c3) \
        : "r"(a0), "r"(a1), "r"(a2), "r"(a3), "r"(b0), "r"(b1))
#define MMA_F16(c0,c1,c2,c3,a0,a1,a2,a3,b0,b1) \
    asm volatile("mma.sync.aligned.m16n8k16.row.col.f32.f16.f16.f32 " \
        "{%0,%1,%2,%3},{%4,%5,%6,%7},{%8,%9},{%0,%1,%2,%3};" \
        : "+f"(c0), "+f"(c1), "+f"(c2), "+f"(c3) \
        : "r"(a0), "r"(a1), "r"(a2), "r"(a3), "r"(b0), "r"(b1))

/* ======================= kernel 1: GIN per tree ========================== */
__global__ void __launch_bounds__(512, 1)
gin_kernel(const int* __restrict__ edge, const int* __restrict__ sp,
           const u8* __restrict__ leaf, const float* __restrict__ emb,
           const float* __restrict__ W1, const float* __restrict__ b1,
           const float* __restrict__ W2, const float* __restrict__ b2,
           const float* __restrict__ eps, const float* __restrict__ gam,
           const float* __restrict__ bet)
{
    extern __shared__ float smf[];
    float* xb   = smf;
    float* vec  = smf + 26000;
    int*   ipar = (int*)(smf + 26256);
    int*   ioff = ipar + 400;
    int*   ilist= ioff + 401;
    int*   soff = ilist + 400;
    int*   slist= soff + 204;
    short* ssp  = (short*)(slist + 400);
    u8*    slf  = (u8*)(ssp + 400);
    __half* hbf = (__half*)((char*)smf + GIN_HOFF);
    __half* wbf = (__half*)((char*)smf + GIN_WOFF);

    const int tid = threadIdx.x;
    const int g   = blockIdx.x;
    const int lane = tid & 31, wrp = tid >> 5;
    const int em  = (edge[1] == 0) ? 2 : 1;
    const int smu = (sp[1]   == 0) ? 2 : 1;
    const int bw  = leaf[1] ? 1 : (leaf[4] ? 4 : 8);

    for (int n = tid; n < NN; n += 512) {
        size_t gi = (size_t)g*NN + n;
        int s = sp[(size_t)smu * gi];
        ssp[n] = (short)s;
        slf[n] = (s >= 0 && leaf[gi * (size_t)bw] != 0) ? 1 : 0;
    }
    for (int n = tid; n <= NN;  n += 512) ioff[n] = 0;
    for (int s = tid; s <= NSP; s += 512) soff[s] = 0;
    __syncthreads();

    for (int i = tid; i < NN*DD; i += 512) {
        int n = i >> 6, d = i & 63;
        int s = ssp[n];
        xb[n*RS + d] = emb[(s < 0 ? NSP : s)*DD + d];
    }
    for (int e = tid; e < EPT; e += 512) {
        int p = edge[(size_t)em * ((size_t)ECOLS + (size_t)g*EPT + e)] - g*NN;
        ipar[e+1] = p;
        atomicAdd(&ioff[p], 1);
    }
    if (tid == 0) ipar[0] = 0;
    for (int n = tid; n < NN; n += 512)
        if (slf[n]) atomicAdd(&soff[ssp[n]], 1);
    __syncthreads();

    if (wrp == 0) {
        int carry = 0;
        for (int base = 0; base < NN; base += 32) {
            int idx = base + lane;
            int orig = (idx < NN) ? ioff[idx] : 0;
            int v = orig;
            #pragma unroll
            for (int o = 1; o < 32; o <<= 1) { int t = __shfl_up_sync(0xffffffffu, v, o); if (lane >= o) v += t; }
            if (idx < NN) ioff[idx] = carry + v - orig;
            carry += __shfl_sync(0xffffffffu, v, 31);
        }
        if (lane == 0) ioff[NN] = carry;
    } else if (wrp == 1) {
        int carry = 0;
        for (int base = 0; base < NSP; base += 32) {
            int idx = base + lane;
            int orig = (idx < NSP) ? soff[idx] : 0;
            int v = orig;
            #pragma unroll
            for (int o = 1; o < 32; o <<= 1) { int t = __shfl_up_sync(0xffffffffu, v, o); if (lane >= o) v += t; }
            if (idx < NSP) soff[idx] = carry + v - orig;
            carry += __shfl_sync(0xffffffffu, v, 31);
        }
        if (lane == 0) soff[NSP] = carry;
    }
    __syncthreads();

    for (int c = 1 + tid; c < NN; c += 512) {
        int p = ipar[c], r = 0;
        for (int c2 = 1; c2 < c; c2++) r += (ipar[c2] == p);
        ilist[ioff[p] + r] = c;
    }
    for (int n = tid; n < NN; n += 512) {
        if (slf[n]) {
            int s = ssp[n], r = 0;
            for (int n2 = 0; n2 < n; n2++) r += (slf[n2] && ssp[n2] == s);
            slist[soff[s] + r] = n;
        }
    }
    __syncthreads();

    const u32 hbf_u = smem_u32(hbf);
    const u32 wbf_u = smem_u32(wbf);
    const u32 a_row = (u32)((lane & 7) + ((lane >> 3) & 1)*8);
    const u32 a_kk  = (u32)((lane >> 4)*8);
    const u32 w_row = (u32)((lane & 7) + ((lane >> 3) & 1)*8);
    const u32 w_col = (u32)((lane >> 4)*8);

    for (int l = 0; l < 2; l++) {
        const float* W1l = W1 + l*DD*DD;
        const float* W2l = W2 + l*DD*DD;
        if (tid < 64) {
            vec[tid]       = b1[l*DD + tid];
            vec[64 + tid]  = b2[l*DD + tid];
            vec[128 + tid] = gam[l*DD + tid];
            vec[192 + tid] = bet[l*DD + tid];
        }
        for (int i = tid; i < DD*DD; i += 512)
            wbf[(i >> 6)*HS + (i & 63)] = __float2half_rn(W1l[i]);
        const float e1 = 1.f + eps[l];
        __syncthreads();

        for (int i = tid; i < NN*DD; i += 512) {
            int n = i >> 6, d = i & 63;
            float a = e1 * xb[n*RS + d];
            if (n > 0) a += xb[ipar[n]*RS + d];
            int o1 = ioff[n+1];
            for (int j = ioff[n]; j < o1; j++) a += xb[ilist[j]*RS + d];
            hbf[n*HS + d] = __float2half_rn(a);
        }
        __syncthreads();

        for (int c0 = wrp; c0 < 25; c0 += 16) {
            int m0 = c0*16;
            float acc[8][4];
            #pragma unroll
            for (int nt = 0; nt < 8; nt++)
                #pragma unroll
                for (int q = 0; q < 4; q++) acc[nt][q] = 0.f;
            #pragma unroll
            for (int ks = 0; ks < 4; ks++) {
                u32 a0,a1,a2,a3;
                LDSM_X4(a0,a1,a2,a3, hbf_u + (((u32)m0 + a_row)*HS + (u32)ks*16 + a_kk)*2);
                u32 b[8][2];
                #pragma unroll
                for (int np = 0; np < 4; np++)
                    LDSM_X4_T(b[np*2][0], b[np*2][1], b[np*2+1][0], b[np*2+1][1],
                              wbf_u + (((u32)ks*16 + w_row)*HS + (u32)np*16 + w_col)*2);
                #pragma unroll
                for (int nt = 0; nt < 8; nt++)
                    MMA_F16(acc[nt][0],acc[nt][1],acc[nt][2],acc[nt][3],
                            a0,a1,a2,a3, b[nt][0],b[nt][1]);
            }
            int r0 = m0 + (lane >> 2), r1 = r0 + 8;
            #pragma unroll
            for (int nt = 0; nt < 8; nt++) {
                int col = nt*8 + (lane & 3)*2;
                float bb0 = vec[col], bb1 = vec[col+1];
                *(__half2*)&hbf[r0*HS + col] = __floats2half2_rn(
                    fmaxf(acc[nt][0] + bb0, 0.f), fmaxf(acc[nt][1] + bb1, 0.f));
                *(__half2*)&hbf[r1*HS + col] = __floats2half2_rn(
                    fmaxf(acc[nt][2] + bb0, 0.f), fmaxf(acc[nt][3] + bb1, 0.f));
            }
        }
        __syncthreads();

        for (int i = tid; i < DD*DD; i += 512)
            wbf[(i >> 6)*HS + (i & 63)] = __float2half_rn(W2l[i]);
        __syncthreads();

        for (int c0 = wrp; c0 < 25; c0 += 16) {
            int m0 = c0*16;
            float acc[8][4];
            #pragma unroll
            for (int nt = 0; nt < 8; nt++)
                #pragma unroll
                for (int q = 0; q < 4; q++) acc[nt][q] = 0.f;
            #pragma unroll
            for (int ks = 0; ks < 4; ks++) {
                u32 a0,a1,a2,a3;
                LDSM_X4(a0,a1,a2,a3, hbf_u + (((u32)m0 + a_row)*HS + (u32)ks*16 + a_kk)*2);
                u32 b[8][2];
                #pragma unroll
                for (int np = 0; np < 4; np++)
                    LDSM_X4_T(b[np*2][0], b[np*2][1], b[np*2+1][0], b[np*2+1][1],
                              wbf_u + (((u32)ks*16 + w_row)*HS + (u32)np*16 + w_col)*2);
                #pragma unroll
                for (int nt = 0; nt < 8; nt++)
                    MMA_F16(acc[nt][0],acc[nt][1],acc[nt][2],acc[nt][3],
                            a0,a1,a2,a3, b[nt][0],b[nt][1]);
            }
            int r0 = m0 + (lane >> 2), r1 = r0 + 8;
            float y0[16], y1[16];
            #pragma unroll
            for (int nt = 0; nt < 8; nt++) {
                int col = nt*8 + (lane & 3)*2;
                float b20 = vec[64+col], b21 = vec[64+col+1];
                y0[2*nt]   = acc[nt][0] + b20 + xb[r0*RS + col];
                y0[2*nt+1] = acc[nt][1] + b21 + xb[r0*RS + col+1];
                y1[2*nt]   = acc[nt][2] + b20 + xb[r1*RS + col];
                y1[2*nt+1] = acc[nt][3] + b21 + xb[r1*RS + col+1];
            }
            float s0 = 0.f, s1 = 0.f;
            #pragma unroll
            for (int q = 0; q < 16; q++) { s0 += y0[q]; s1 += y1[q]; }
            s0 += __shfl_xor_sync(0xffffffffu, s0, 1);
            s0 += __shfl_xor_sync(0xffffffffu, s0, 2);
            s1 += __shfl_xor_sync(0xffffffffu, s1, 1);
            s1 += __shfl_xor_sync(0xffffffffu, s1, 2);
            float mu0 = s0*(1.f/DD), mu1 = s1*(1.f/DD);
            float v0 = 0.f, v1 = 0.f;
            #pragma unroll
            for (int q = 0; q < 16; q++) {
                float d0 = y0[q]-mu0, d1 = y1[q]-mu1;
                v0 = fmaf(d0,d0,v0); v1 = fmaf(d1,d1,v1);
            }
            v0 += __shfl_xor_sync(0xffffffffu, v0, 1);
            v0 += __shfl_xor_sync(0xffffffffu, v0, 2);
            v1 += __shfl_xor_sync(0xffffffffu, v1, 1);
            v1 += __shfl_xor_sync(0xffffffffu, v1, 2);
            float rs0 = rsqrtf(v0*(1.f/DD) + 1e-5f);
            float rs1 = rsqrtf(v1*(1.f/DD) + 1e-5f);
            #pragma unroll
            for (int nt = 0; nt < 8; nt++) {
                int col = nt*8 + (lane & 3)*2;
                xb[r0*RS + col]   = (y0[2*nt]  -mu0)*rs0*vec[128+col]   + vec[192+col];
                xb[r0*RS + col+1] = (y0[2*nt+1]-mu0)*rs0*vec[128+col+1] + vec[192+col+1];
                xb[r1*RS + col]   = (y1[2*nt]  -mu1)*rs1*vec[128+col]   + vec[192+col];
                xb[r1*RS + col+1] = (y1[2*nt+1]-mu1)*rs1*vec[128+col+1] + vec[192+col+1];
            }
        }
        __syncthreads();
    }

    /* species pooling -> bf16 pool + fp32 valid */
    for (int i = tid; i < NSP*DD; i += 512) {
        int s = i >> 6, d = i & 63;
        int o0 = soff[s], o1 = soff[s+1];
        float a = 0.f;
        for (int j = o0; j < o1; j++) a += xb[slist[j]*RS + d];
        float c = (float)(o1 - o0);
        g_pool_bf[(size_t)s*NGT*DD + (size_t)g*DD + d] = __float2bfloat16(a / fmaxf(c, 1.f));
        if (d == 0) g_valid[s*NGT + g] = (c > 0.f) ? 1.f : 0.f;
    }
}

/* =============== kernel 2b: build bf16 mask A [EPAD x KPAD] ============= */
__global__ void maskprep_kernel(const u8* __restrict__ clade, const u8* __restrict__ leaf)
{
    const int e = blockIdx.x, s = threadIdx.x;   /* grid EPAD, block KPAD */
    const int bw = leaf[1] ? 1 : (leaf[4] ? 4 : 8);
    float v = 0.f;
    if (e < NED && s < NSP && clade[((size_t)e*NSP + s)*(size_t)bw]) v = 1.f;
    g_maskA[(size_t)e*KPAD + s] = __float2bfloat16(v);
}

/* =========== kernel 2c: tiled transpose pool -> poolT [gd][s] =========== */
__global__ void __launch_bounds__(256)
transpose_kernel()
{
    __shared__ u16 t[32][40];
    const int tid = threadIdx.x;
    const int gd0 = blockIdx.x * 32;   /* GTS/32 = 1024 */
    const int s0  = blockIdx.y * 32;   /* 7 tiles cover 208 */
    for (int i = tid; i < 1024; i += 256) {
        int sr = i >> 5, gdc = i & 31;
        int s = s0 + sr;
        t[sr][gdc] = (s < NSP) ? *(const u16*)&g_pool_bf[(size_t)s*GTS + gd0 + gdc] : (u16)0;
    }
    __syncthreads();
    for (int i = tid; i < 1024; i += 256) {
        int gdr = i >> 5, sc = i & 31;
        if (s0 + sc < KPAD)
            *(u16*)&g_poolT[(size_t)(gd0 + gdr)*KPAD + s0 + sc] = t[sc][gdr];
    }
}

/* ====== kernel 2d: transpose valid [s][g] fp32 -> validT [g][s] bf16 ==== */
__global__ void __launch_bounds__(256)
validT_kernel()
{
    __shared__ u16 t[32][40];
    const int tid = threadIdx.x;
    const int g0 = blockIdx.x * 32;    /* NGT/32 = 16 */
    const int s0 = blockIdx.y * 32;    /* 7 tiles cover 208 */
    for (int i = tid; i < 1024; i += 256) {
        int sr = i >> 5, gc = i & 31;
        int s = s0 + sr;
        float v = (s < NSP) ? g_valid[s*NGT + g0 + gc] : 0.f;
        __nv_bfloat16 b = __float2bfloat16(v);
        t[sr][gc] = *(u16*)&b;
    }
    __syncthreads();
    for (int i = tid; i < 1024; i += 256) {
        int gr = i >> 5, sc = i & 31;
        if (s0 + sc < KPAD)
            *(u16*)&g_validT[(size_t)(g0 + gr)*KPAD + s0 + sc] = t[sc][gr];
    }
}

/* ====== kernel 3: mma.sync bf16 GEMM  C[e,gd] = sum_s M[e,s] P[gd,s] ==== */
#define APAD 216
#define SMA_OFF 0
#define SMB_OFF (128*APAD*2)               /* 55296 */
#define SMIV_OFF (SMB_OFF + 64*APAD*2)     /* +27648 = 82944 */
#define SMG_TOT (SMIV_OFF + 128*4)         /* 83456 */

__global__ void __launch_bounds__(256, 1)
gemm_mma_kernel()
{
    extern __shared__ char smg[];
    const u32 smem = smem_u32(smg);
    __nv_bfloat16* smA = (__nv_bfloat16*)(smg + SMA_OFF);
    __nv_bfloat16* smB = (__nv_bfloat16*)(smg + SMB_OFF);
    float*         smIv= (float*)(smg + SMIV_OFF);

    const int tid  = threadIdx.x;
    const int lane = tid & 31, wrp = tid >> 5;
    const int wm   = wrp >> 1, wn = wrp & 1;
    const int gq    = blockIdx.x;
    const int etile = blockIdx.y;

    for (int i = tid; i < 128*KQ4; i += 256) {
        int m = i / KQ4, kq = i % KQ4;
        *(uint4*)&smA[m*APAD + kq*8] =
            *(const uint4*)&g_maskA[(size_t)(etile*128 + m)*KPAD + kq*8];
    }

    const u32 a_row = (u32)(wm*32 + (lane & 7) + ((lane >> 3) & 1)*8);
    const u32 a_kk  = (u32)((lane >> 4)*8);
    const u32 b_row = (u32)(wn*32 + (lane & 7) + (lane >> 4)*8);
    const u32 b_kk  = (u32)(((lane >> 3) & 1)*8);
    const u32 aBase = smem + SMA_OFF;
    const u32 bBase = smem + SMB_OFF;

    for (int gi = 0; gi < 4; gi++) {
        const int g = gq*4 + gi;
        __syncthreads();
        for (int i = tid; i < 64*KQ4; i += 256) {
            int n = i / KQ4, kq = i % KQ4;
            *(uint4*)&smB[n*APAD + kq*8] =
                *(const uint4*)&g_poolT[(size_t)(g*64 + n)*KPAD + kq*8];
        }
        if (tid < 128)
            smIv[tid] = g_minv[(size_t)(etile*128 + tid)*NGT + g];
        __syncthreads();

        float c[2][4][4];
        #pragma unroll
        for (int mf = 0; mf < 2; mf++)
            #pragma unroll
            for (int nf = 0; nf < 4; nf++)
                #pragma unroll
                for (int q = 0; q < 4; q++) c[mf][nf][q] = 0.f;

        #pragma unroll 4
        for (int ks = 0; ks < 13; ks++) {
            u32 a[2][4], b[4][2];
            #pragma unroll
            for (int mf = 0; mf < 2; mf++) {
                u32 ad = aBase + ((a_row + mf*16)*APAD + ks*16 + a_kk)*2;
                LDSM_X4(a[mf][0], a[mf][1], a[mf][2], a[mf][3], ad);
            }
            #pragma unroll
            for (int nh = 0; nh < 2; nh++) {
                u32 bd = bBase + ((b_row + nh*16)*APAD + ks*16 + b_kk)*2;
                LDSM_X4(b[nh*2][0], b[nh*2][1], b[nh*2+1][0], b[nh*2+1][1], bd);
            }
            #pragma unroll
            for (int mf = 0; mf < 2; mf++)
                #pragma unroll
                for (int nf = 0; nf < 4; nf++)
                    MMA_BF16(c[mf][nf][0], c[mf][nf][1], c[mf][nf][2], c[mf][nf][3],
                             a[mf][0], a[mf][1], a[mf][2], a[mf][3],
                             b[nf][0], b[nf][1]);
        }

        #pragma unroll
        for (int mf = 0; mf < 2; mf++) {
            int mLoc = wm*32 + mf*16 + (lane >> 2);
            int eLo = etile*128 + mLoc;
            int eHi = eLo + 8;
            float ivLo = smIv[mLoc], ivHi = smIv[mLoc + 8];
            #pragma unroll
            for (int nf = 0; nf < 4; nf++) {
                int d = wn*32 + nf*8 + (lane & 3)*2;
                if (eLo < NED) {
                    float2 v; v.x = c[mf][nf][0]*ivLo; v.y = c[mf][nf][1]*ivLo;
                    *(float2*)&g_gt[(size_t)eLo*GTS + g*64 + d] = v;
                }
                if (eHi < NED) {
                    float2 v; v.x = c[mf][nf][2]*ivHi; v.y = c[mf][nf][3]*ivHi;
                    *(float2*)&g_gt[(size_t)eHi*GTS + g*64 + d] = v;
                }
            }
        }
    }
}

/* ====== kernel 2e: ccnt GEMM -> minv  (exact bf16 0/1 x 0/1 MMA) ======== */
#define SMCB_OFF (128*APAD*2)
#define SMC_TOT  (2*128*APAD*2)            /* 110592 */

__global__ void __launch_bounds__(256, 1)
cntmma_kernel()
{
    extern __shared__ char smcc[];
    const u32 smem = smem_u32(smcc);
    __nv_bfloat16* smA = (__nv_bfloat16*)(smcc);
    __nv_bfloat16* smB = (__nv_bfloat16*)(smcc + SMCB_OFF);

    const int tid  = threadIdx.x;
    const int lane = tid & 31, wrp = tid >> 5;
    const int wm   = wrp >> 1, wn = wrp & 1;   /* warp tile 32e x 64g */
    const int gtile = blockIdx.x;              /* 4 tiles of 128 g */
    const int etile = blockIdx.y;              /* 4 tiles of 128 e */

    for (int i = tid; i < 128*KQ4; i += 256) {
        int m = i / KQ4, kq = i % KQ4;
        *(uint4*)&smA[m*APAD + kq*8] =
            *(const uint4*)&g_maskA[(size_t)(etile*128 + m)*KPAD + kq*8];
        *(uint4*)&smB[m*APAD + kq*8] =
            *(const uint4*)&g_validT[(size_t)(gtile*128 + m)*KPAD + kq*8];
    }
    __syncthreads();

    const u32 a_row = (u32)(wm*32 + (lane & 7) + ((lane >> 3) & 1)*8);
    const u32 a_kk  = (u32)((lane >> 4)*8);
    const u32 b_row = (u32)(wn*64 + (lane & 7) + (lane >> 4)*8);
    const u32 b_kk  = (u32)(((lane >> 3) & 1)*8);
    const u32 aBase = smem;
    const u32 bBase = smem + SMCB_OFF;

    float c[2][8][4];
    #pragma unroll
    for (int mf = 0; mf < 2; mf++)
        #pragma unroll
        for (int nf = 0; nf < 8; nf++)
            #pragma unroll
            for (int q = 0; q < 4; q++) c[mf][nf][q] = 0.f;

    for (int ks = 0; ks < 13; ks++) {
        u32 a[2][4], b[8][2];
        #pragma unroll
        for (int mf = 0; mf < 2; mf++) {
            u32 ad = aBase + ((a_row + mf*16)*APAD + ks*16 + a_kk)*2;
            LDSM_X4(a[mf][0], a[mf][1], a[mf][2], a[mf][3], ad);
        }
        #pragma unroll
        for (int nh = 0; nh < 4; nh++) {
            u32 bd = bBase + ((b_row + nh*16)*APAD + ks*16 + b_kk)*2;
            LDSM_X4(b[nh*2][0], b[nh*2][1], b[nh*2+1][0], b[nh*2+1][1], bd);
        }
        #pragma unroll
        for (int mf = 0; mf < 2; mf++)
            #pragma unroll
            for (int nf = 0; nf < 8; nf++)
                MMA_BF16(c[mf][nf][0], c[mf][nf][1], c[mf][nf][2], c[mf][nf][3],
                         a[mf][0], a[mf][1], a[mf][2], a[mf][3],
                         b[nf][0], b[nf][1]);
    }

    #pragma unroll
    for (int mf = 0; mf < 2; mf++) {
        int eLo = etile*128 + wm*32 + mf*16 + (lane >> 2);
        int eHi = eLo + 8;
        #pragma unroll
        for (int nf = 0; nf < 8; nf++) {
            int gg = gtile*128 + wn*64 + nf*8 + (lane & 3)*2;
            if (eLo < NED) {
                float2 v;
                v.x = (c[mf][nf][0] > 0.f) ? (1.f/c[mf][nf][0]) : 0.f;
                v.y = (c[mf][nf][1] > 0.f) ? (1.f/c[mf][nf][1]) : 0.f;
                *(float2*)&g_minv[(size_t)eLo*NGT + gg] = v;
            }
            if (eHi < NED) {
                float2 v;
                v.x = (c[mf][nf][2] > 0.f) ? (1.f/c[mf][nf][2]) : 0.f;
                v.y = (c[mf][nf][3] > 0.f) ? (1.f/c[mf][nf][3]) : 0.f;
                *(float2*)&g_minv[(size_t)eHi*NGT + gg] = v;
            }
        }
    }
}

/* ========= kernel 4: per-edge mean / unbiased std (single pass) ========= */
__global__ void __launch_bounds__(256, 4)
stats_kernel(float* __restrict__ out)
{
    __shared__ float red1[256], red2[256], redc[256];
    const int e = blockIdx.x, tid = threadIdx.x;
    const int d = tid & 63, part = tid >> 6;
    const float* gt = g_gt + (size_t)e*GTS;

    float s1 = 0.f, s2 = 0.f, cnt = 0.f;
    for (int gg = part*128; gg < part*128 + 128; gg++) {
        float x = gt[gg*DD + d];
        s1 += x;
        s2 = fmaf(x, x, s2);
        cnt += (g_minv[(size_t)e*NGT + gg] > 0.f) ? 1.f : 0.f;
    }
    red1[tid] = s1; red2[tid] = s2; redc[tid] = cnt;
    __syncthreads();
    if (tid < 64) {
        float nv = redc[d] + redc[64+d] + redc[128+d] + redc[192+d];
        float t1 = red1[d] + red1[64+d] + red1[128+d] + red1[192+d];
        float t2 = red2[d] + red2[64+d] + red2[128+d] + red2[192+d];
        float mn = t1 / fmaxf(nv, 1.f);
        float var = (t2 - nv*mn*mn) / fmaxf(nv - 1.f, 1.f);
        var = fmaxf(var, 0.f);
        out[(size_t)e*2*DD + d]      = mn;
        out[(size_t)e*2*DD + DD + d] = (nv > 1.f) ? sqrtf(var) : 0.f;
    }
}

/* ------------------------------ host -------------------------------------*/
extern "C" void kernel_launch(void* const* d_in, const int* in_sizes, int n_in,
                              void* d_out, int out_size)
{
    int o = (n_in > 5 && in_sizes[5] == (NSP+1)*DD) ? 0 : 1;

    const int* edge = (const int*)d_in[0];
    const int* sp   = (const int*)d_in[1];
    const u8*  leaf = (const u8*)d_in[2];
    const u8*  clad = (const u8*)d_in[4];
    const float* emb = (const float*)d_in[5+o];
    const float* W1  = (const float*)d_in[6+o];
    const float* b1  = (const float*)d_in[7+o];
    const float* W2  = (const float*)d_in[8+o];
    const float* b2  = (const float*)d_in[9+o];
    const float* eps = (const float*)d_in[10+o];
    const float* gam = (const float*)d_in[11+o];
    const float* bet = (const float*)d_in[12+o];

    cudaFuncSetAttribute(gin_kernel,      cudaFuncAttributeMaxDynamicSharedMemorySize, GIN_SMEM);
    cudaFuncSetAttribute(gemm_mma_kernel, cudaFuncAttributeMaxDynamicSharedMemorySize, SMG_TOT);
    cudaFuncSetAttribute(cntmma_kernel,   cudaFuncAttributeMaxDynamicSharedMemorySize, SMC_TOT);

    gin_kernel<<<NGT, 512, GIN_SMEM>>>(edge, sp, leaf, emb, W1, b1, W2, b2, eps, gam, bet);
    maskprep_kernel<<<EPAD, KPAD>>>(clad, leaf);
    transpose_kernel<<<dim3(GTS/32, 7), 256>>>();
    validT_kernel<<<dim3(NGT/32, 7), 256>>>();
    cntmma_kernel<<<dim3(4, 4), 256, SMC_TOT>>>();
    gemm_mma_kernel<<<dim3(128, 4), 256, SMG_TOT>>>();
    stats_kernel<<<NED, 256>>>((float*)d_out);
    (void)out_size; (void)n_in;
}

// round 14
// speedup vs baseline: 1.0612x; 1.0612x over previous
#include <cuda_runtime.h>
#include <cuda_bf16.h>
#include <cuda_fp16.h>
#include <cstdint>

#define NGT 512
#define NN  399
#define NSP 200
#define NED 397
#define DD  64
#define EPT 398
#define ECOLS (NGT*EPT*2)
#define RS  65
#define HS  72                 /* fp16 row stride (conflict-free ldmatrix) */
#define GTS (NGT*DD)
#define KPAD 256
#define EPAD 512
#define NT  800                /* 25 warps: one 16-row chunk per warp */

/* gin smem layout (bytes) */
#define GIN_HOFF 113456
#define GIN_WOFF 171056
#define GIN_SMEM 180272

typedef unsigned char u8;
typedef unsigned long long ull;
typedef unsigned int u32;
typedef unsigned short u16;

/* ---------------- scratch (static device globals) ----------------------- */
__device__ __nv_bfloat16 g_pool_bf[(size_t)NSP*NGT*DD];   /* [s][g][d] 13MB */
__device__ __nv_bfloat16 g_poolT[(size_t)GTS*KPAD];       /* [gd][s] 16.8MB */
__device__ __nv_bfloat16 g_maskA[(size_t)EPAD*KPAD];      /* [e][s] */
__device__ float g_valid[NSP*NGT];                        /* [s][g] */
__device__ float g_gt[(size_t)400*GTS];                   /* [e][g][d] 52MB */
__device__ float g_minv[(size_t)EPAD*NGT];                /* [e][g] */

__device__ __forceinline__ u32 smem_u32(const void* p){
    u32 a; asm("{ .reg .u64 t; cvta.to.shared.u64 t, %1; cvt.u32.u64 %0, t; }" : "=r"(a) : "l"(p));
    return a;
}
#define LDSM_X4(r0,r1,r2,r3,addr) \
    asm volatile("ldmatrix.sync.aligned.m8n8.x4.shared.b16 {%0,%1,%2,%3}, [%4];" \
        : "=r"(r0), "=r"(r1), "=r"(r2), "=r"(r3) : "r"(addr))
#define LDSM_X4_T(r0,r1,r2,r3,addr) \
    asm volatile("ldmatrix.sync.aligned.m8n8.x4.trans.shared.b16 {%0,%1,%2,%3}, [%4];" \
        : "=r"(r0), "=r"(r1), "=r"(r2), "=r"(r3) : "r"(addr))
#define MMA_BF16(c0,c1,c2,c3,a0,a1,a2,a3,b0,b1) \
    asm volatile("mma.sync.aligned.m16n8k16.row.col.f32.bf16.bf16.f32 " \
        "{%0,%1,%2,%3},{%4,%5,%6,%7},{%8,%9},{%0,%1,%2,%3};" \
        : "+f"(c0), "+f"(c1), "+f"(c2), "+f"(c3) \
        : "r"(a0), "r"(a1), "r"(a2), "r"(a3), "r"(b0), "r"(b1))
#define MMA_F16(c0,c1,c2,c3,a0,a1,a2,a3,b0,b1) \
    asm volatile("mma.sync.aligned.m16n8k16.row.col.f32.f16.f16.f32 " \
        "{%0,%1,%2,%3},{%4,%5,%6,%7},{%8,%9},{%0,%1,%2,%3};" \
        : "+f"(c0), "+f"(c1), "+f"(c2), "+f"(c3) \
        : "r"(a0), "r"(a1), "r"(a2), "r"(a3), "r"(b0), "r"(b1))

/* ======================= kernel 1: GIN per tree ========================== */
__global__ void __launch_bounds__(NT, 1)
gin_kernel(const int* __restrict__ edge, const int* __restrict__ sp,
           const u8* __restrict__ leaf, const float* __restrict__ emb,
           const float* __restrict__ W1, const float* __restrict__ b1,
           const float* __restrict__ W2, const float* __restrict__ b2,
           const float* __restrict__ eps, const float* __restrict__ gam,
           const float* __restrict__ bet)
{
    extern __shared__ float smf[];
    float* xb   = smf;                       /* 400 x 65 fp32 */
    float* vec  = smf + 26000;               /* b1|b2|gamma|beta */
    int*   ipar = (int*)(smf + 26256);       /* 400 */
    int*   ioff = ipar + 400;                /* 401 */
    int*   ilist= ioff + 401;                /* 400 */
    int*   soff = ilist + 400;               /* 204 */
    int*   slist= soff + 204;                /* 400 */
    short* ssp  = (short*)(slist + 400);     /* 400 */
    u8*    slf  = (u8*)(ssp + 400);          /* 400 */
    __half* hbf = (__half*)((char*)smf + GIN_HOFF);  /* 400 x HS */
    __half* wbf = (__half*)((char*)smf + GIN_WOFF);  /* 64 x HS  */

    const int tid = threadIdx.x;
    const int g   = blockIdx.x;
    const int lane = tid & 31, wrp = tid >> 5;
    const int em  = (edge[1] == 0) ? 2 : 1;
    const int smu = (sp[1]   == 0) ? 2 : 1;
    const int bw  = leaf[1] ? 1 : (leaf[4] ? 4 : 8);

    for (int n = tid; n < NN; n += NT) {
        size_t gi = (size_t)g*NN + n;
        int s = sp[(size_t)smu * gi];
        ssp[n] = (short)s;
        slf[n] = (s >= 0 && leaf[gi * (size_t)bw] != 0) ? 1 : 0;
    }
    for (int n = tid; n <= NN;  n += NT) ioff[n] = 0;
    for (int s = tid; s <= NSP; s += NT) soff[s] = 0;
    __syncthreads();

    for (int i = tid; i < NN*DD; i += NT) {
        int n = i >> 6, d = i & 63;
        int s = ssp[n];
        xb[n*RS + d] = emb[(s < 0 ? NSP : s)*DD + d];
    }
    for (int e = tid; e < EPT; e += NT) {
        int p = edge[(size_t)em * ((size_t)ECOLS + (size_t)g*EPT + e)] - g*NN;
        ipar[e+1] = p;
        atomicAdd(&ioff[p], 1);
    }
    if (tid == 0) ipar[0] = 0;
    for (int n = tid; n < NN; n += NT)
        if (slf[n]) atomicAdd(&soff[ssp[n]], 1);
    __syncthreads();

    /* exclusive scans */
    if (wrp == 0) {
        int carry = 0;
        for (int base = 0; base < NN; base += 32) {
            int idx = base + lane;
            int orig = (idx < NN) ? ioff[idx] : 0;
            int v = orig;
            #pragma unroll
            for (int o = 1; o < 32; o <<= 1) { int t = __shfl_up_sync(0xffffffffu, v, o); if (lane >= o) v += t; }
            if (idx < NN) ioff[idx] = carry + v - orig;
            carry += __shfl_sync(0xffffffffu, v, 31);
        }
        if (lane == 0) ioff[NN] = carry;
    } else if (wrp == 1) {
        int carry = 0;
        for (int base = 0; base < NSP; base += 32) {
            int idx = base + lane;
            int orig = (idx < NSP) ? soff[idx] : 0;
            int v = orig;
            #pragma unroll
            for (int o = 1; o < 32; o <<= 1) { int t = __shfl_up_sync(0xffffffffu, v, o); if (lane >= o) v += t; }
            if (idx < NSP) soff[idx] = carry + v - orig;
            carry += __shfl_sync(0xffffffffu, v, 31);
        }
        if (lane == 0) soff[NSP] = carry;
    }
    __syncthreads();

    /* deterministic CSR fill via rank counting */
    for (int c = 1 + tid; c < NN; c += NT) {
        int p = ipar[c], r = 0;
        for (int c2 = 1; c2 < c; c2++) r += (ipar[c2] == p);
        ilist[ioff[p] + r] = c;
    }
    for (int n = tid; n < NN; n += NT) {
        if (slf[n]) {
            int s = ssp[n], r = 0;
            for (int n2 = 0; n2 < n; n2++) r += (slf[n2] && ssp[n2] == s);
            slist[soff[s] + r] = n;
        }
    }
    __syncthreads();

    /* ldmatrix per-lane address components */
    const u32 hbf_u = smem_u32(hbf);
    const u32 wbf_u = smem_u32(wbf);
    const u32 a_row = (u32)((lane & 7) + ((lane >> 3) & 1)*8);
    const u32 a_kk  = (u32)((lane >> 4)*8);
    const u32 w_row = (u32)((lane & 7) + ((lane >> 3) & 1)*8);  /* k within 16 */
    const u32 w_col = (u32)((lane >> 4)*8);                      /* n within 16 */

    for (int l = 0; l < 2; l++) {
        const float* W1l = W1 + l*DD*DD;
        const float* W2l = W2 + l*DD*DD;
        if (tid < 64) {
            vec[tid]       = b1[l*DD + tid];
            vec[64 + tid]  = b2[l*DD + tid];
            vec[128 + tid] = gam[l*DD + tid];
            vec[192 + tid] = bet[l*DD + tid];
        }
        /* stage W1 fp16 */
        for (int i = tid; i < DD*DD; i += NT)
            wbf[(i >> 6)*HS + (i & 63)] = __float2half_rn(W1l[i]);
        const float e1 = 1.f + eps[l];
        __syncthreads();

        /* gather -> h (fp32 math, fp16 store) */
        for (int i = tid; i < NN*DD; i += NT) {
            int n = i >> 6, d = i & 63;
            float a = e1 * xb[n*RS + d];
            if (n > 0) a += xb[ipar[n]*RS + d];
            int o1 = ioff[n+1];
            for (int j = ioff[n]; j < o1; j++) a += xb[ilist[j]*RS + d];
            hbf[n*HS + d] = __float2half_rn(a);
        }
        __syncthreads();

        /* matmul1: t = relu(h @ W1 + b1) -> hbf (one chunk per warp) */
        for (int c0 = wrp; c0 < 25; c0 += 25) {
            int m0 = c0*16;
            float acc[8][4];
            #pragma unroll
            for (int nt = 0; nt < 8; nt++)
                #pragma unroll
                for (int q = 0; q < 4; q++) acc[nt][q] = 0.f;
            #pragma unroll
            for (int ks = 0; ks < 4; ks++) {
                u32 a0,a1,a2,a3;
                LDSM_X4(a0,a1,a2,a3, hbf_u + (((u32)m0 + a_row)*HS + (u32)ks*16 + a_kk)*2);
                u32 b[8][2];
                #pragma unroll
                for (int np = 0; np < 4; np++)
                    LDSM_X4_T(b[np*2][0], b[np*2][1], b[np*2+1][0], b[np*2+1][1],
                              wbf_u + (((u32)ks*16 + w_row)*HS + (u32)np*16 + w_col)*2);
                #pragma unroll
                for (int nt = 0; nt < 8; nt++)
                    MMA_F16(acc[nt][0],acc[nt][1],acc[nt][2],acc[nt][3],
                            a0,a1,a2,a3, b[nt][0],b[nt][1]);
            }
            int r0 = m0 + (lane >> 2), r1 = r0 + 8;
            #pragma unroll
            for (int nt = 0; nt < 8; nt++) {
                int col = nt*8 + (lane & 3)*2;
                float bb0 = vec[col], bb1 = vec[col+1];
                *(__half2*)&hbf[r0*HS + col] = __floats2half2_rn(
                    fmaxf(acc[nt][0] + bb0, 0.f), fmaxf(acc[nt][1] + bb1, 0.f));
                *(__half2*)&hbf[r1*HS + col] = __floats2half2_rn(
                    fmaxf(acc[nt][2] + bb0, 0.f), fmaxf(acc[nt][3] + bb1, 0.f));
            }
        }
        __syncthreads();

        /* stage W2 fp16 */
        for (int i = tid; i < DD*DD; i += NT)
            wbf[(i >> 6)*HS + (i & 63)] = __float2half_rn(W2l[i]);
        __syncthreads();

        /* matmul2 + residual + LayerNorm -> xb (one chunk per warp) */
        for (int c0 = wrp; c0 < 25; c0 += 25) {
            int m0 = c0*16;
            float acc[8][4];
            #pragma unroll
            for (int nt = 0; nt < 8; nt++)
                #pragma unroll
                for (int q = 0; q < 4; q++) acc[nt][q] = 0.f;
            #pragma unroll
            for (int ks = 0; ks < 4; ks++) {
                u32 a0,a1,a2,a3;
                LDSM_X4(a0,a1,a2,a3, hbf_u + (((u32)m0 + a_row)*HS + (u32)ks*16 + a_kk)*2);
                u32 b[8][2];
                #pragma unroll
                for (int np = 0; np < 4; np++)
                    LDSM_X4_T(b[np*2][0], b[np*2][1], b[np*2+1][0], b[np*2+1][1],
                              wbf_u + (((u32)ks*16 + w_row)*HS + (u32)np*16 + w_col)*2);
                #pragma unroll
                for (int nt = 0; nt < 8; nt++)
                    MMA_F16(acc[nt][0],acc[nt][1],acc[nt][2],acc[nt][3],
                            a0,a1,a2,a3, b[nt][0],b[nt][1]);
            }
            int r0 = m0 + (lane >> 2), r1 = r0 + 8;
            float y0[16], y1[16];
            #pragma unroll
            for (int nt = 0; nt < 8; nt++) {
                int col = nt*8 + (lane & 3)*2;
                float b20 = vec[64+col], b21 = vec[64+col+1];
                y0[2*nt]   = acc[nt][0] + b20 + xb[r0*RS + col];
                y0[2*nt+1] = acc[nt][1] + b21 + xb[r0*RS + col+1];
                y1[2*nt]   = acc[nt][2] + b20 + xb[r1*RS + col];
                y1[2*nt+1] = acc[nt][3] + b21 + xb[r1*RS + col+1];
            }
            float s0 = 0.f, s1 = 0.f;
            #pragma unroll
            for (int q = 0; q < 16; q++) { s0 += y0[q]; s1 += y1[q]; }
            s0 += __shfl_xor_sync(0xffffffffu, s0, 1);
            s0 += __shfl_xor_sync(0xffffffffu, s0, 2);
            s1 += __shfl_xor_sync(0xffffffffu, s1, 1);
            s1 += __shfl_xor_sync(0xffffffffu, s1, 2);
            float mu0 = s0*(1.f/DD), mu1 = s1*(1.f/DD);
            float v0 = 0.f, v1 = 0.f;
            #pragma unroll
            for (int q = 0; q < 16; q++) {
                float d0 = y0[q]-mu0, d1 = y1[q]-mu1;
                v0 = fmaf(d0,d0,v0); v1 = fmaf(d1,d1,v1);
            }
            v0 += __shfl_xor_sync(0xffffffffu, v0, 1);
            v0 += __shfl_xor_sync(0xffffffffu, v0, 2);
            v1 += __shfl_xor_sync(0xffffffffu, v1, 1);
            v1 += __shfl_xor_sync(0xffffffffu, v1, 2);
            float rs0 = rsqrtf(v0*(1.f/DD) + 1e-5f);
            float rs1 = rsqrtf(v1*(1.f/DD) + 1e-5f);
            #pragma unroll
            for (int nt = 0; nt < 8; nt++) {
                int col = nt*8 + (lane & 3)*2;
                xb[r0*RS + col]   = (y0[2*nt]  -mu0)*rs0*vec[128+col]   + vec[192+col];
                xb[r0*RS + col+1] = (y0[2*nt+1]-mu0)*rs0*vec[128+col+1] + vec[192+col+1];
                xb[r1*RS + col]   = (y1[2*nt]  -mu1)*rs1*vec[128+col]   + vec[192+col];
                xb[r1*RS + col+1] = (y1[2*nt+1]-mu1)*rs1*vec[128+col+1] + vec[192+col+1];
            }
        }
        __syncthreads();
    }

    /* species pooling -> bf16 pool + fp32 valid */
    for (int i = tid; i < NSP*DD; i += NT) {
        int s = i >> 6, d = i & 63;
        int o0 = soff[s], o1 = soff[s+1];
        float a = 0.f;
        for (int j = o0; j < o1; j++) a += xb[slist[j]*RS + d];
        float c = (float)(o1 - o0);
        g_pool_bf[(size_t)s*NGT*DD + (size_t)g*DD + d] = __float2bfloat16(a / fmaxf(c, 1.f));
        if (d == 0) g_valid[s*NGT + g] = (c > 0.f) ? 1.f : 0.f;
    }
}

/* ====== kernel 2: per-(edge,tree) 1/ccnt (1 edge x 256 g per CTA) ======= */
__global__ void __launch_bounds__(256)
cnt_kernel(const u8* __restrict__ clade, const u8* __restrict__ leaf)
{
    __shared__ float msk[NSP];
    const int tid = threadIdx.x;
    const int e   = blockIdx.x;
    const int gg  = blockIdx.y * 256 + tid;
    const int bw  = leaf[1] ? 1 : (leaf[4] ? 4 : 8);
    if (tid < NSP)
        msk[tid] = clade[((size_t)e*NSP + tid)*(size_t)bw] ? 1.f : 0.f;
    __syncthreads();
    float c = 0.f;
    for (int s0 = 0; s0 < NSP; s0 += 8) {
        float v[8];
        #pragma unroll
        for (int q = 0; q < 8; q++) v[q] = g_valid[(s0+q)*NGT + gg];
        #pragma unroll
        for (int q = 0; q < 8; q++) c = fmaf(msk[s0+q], v[q], c);
    }
    g_minv[(size_t)e*NGT + gg] = (c > 0.f) ? (1.f/c) : 0.f;
}

/* =============== kernel 2b: build bf16 mask A [EPAD x KPAD] ============= */
__global__ void maskprep_kernel(const u8* __restrict__ clade, const u8* __restrict__ leaf)
{
    const int e = blockIdx.x, s = threadIdx.x;
    const int bw = leaf[1] ? 1 : (leaf[4] ? 4 : 8);
    float v = 0.f;
    if (e < NED && s < NSP && clade[((size_t)e*NSP + s)*(size_t)bw]) v = 1.f;
    g_maskA[(size_t)e*KPAD + s] = __float2bfloat16(v);
}

/* =========== kernel 2c: tiled transpose pool -> poolT [gd][s] =========== */
__global__ void __launch_bounds__(256)
transpose_kernel()
{
    __shared__ u16 t[32][40];
    const int tid = threadIdx.x;
    const int gd0 = blockIdx.x * 32;
    const int s0  = blockIdx.y * 32;
    for (int i = tid; i < 1024; i += 256) {
        int sr = i >> 5, gdc = i & 31;
        int s = s0 + sr;
        t[sr][gdc] = (s < NSP) ? *(const u16*)&g_pool_bf[(size_t)s*GTS + gd0 + gdc] : (u16)0;
    }
    __syncthreads();
    for (int i = tid; i < 1024; i += 256) {
        int gdr = i >> 5, sc = i & 31;
        *(u16*)&g_poolT[(size_t)(gd0 + gdr)*KPAD + s0 + sc] = t[sc][gdr];
    }
}

/* ====== kernel 3: mma.sync bf16 GEMM  C[e,gd] = sum_s M[e,s] P[gd,s] ==== */
#define APAD 264
#define SMA_OFF 0
#define SMB_OFF (128*APAD*2)
#define SMIV_OFF (SMB_OFF + 64*APAD*2)
#define SMG_TOT (SMIV_OFF + 128*4)

__global__ void __launch_bounds__(256, 1)
gemm_mma_kernel()
{
    extern __shared__ char smg[];
    const u32 smem = smem_u32(smg);
    __nv_bfloat16* smA = (__nv_bfloat16*)(smg + SMA_OFF);
    __nv_bfloat16* smB = (__nv_bfloat16*)(smg + SMB_OFF);
    float*         smIv= (float*)(smg + SMIV_OFF);

    const int tid  = threadIdx.x;
    const int lane = tid & 31, wrp = tid >> 5;
    const int wm   = wrp >> 1, wn = wrp & 1;
    const int gq    = blockIdx.x;
    const int etile = blockIdx.y;

    for (int i = tid; i < 128*32; i += 256) {
        int m = i >> 5, kq = i & 31;
        *(uint4*)&smA[m*APAD + kq*8] =
            *(const uint4*)&g_maskA[(size_t)(etile*128 + m)*KPAD + kq*8];
    }

    const u32 a_row = (u32)(wm*32 + (lane & 7) + ((lane >> 3) & 1)*8);
    const u32 a_kk  = (u32)((lane >> 4)*8);
    const u32 b_row = (u32)(wn*32 + (lane & 7) + (lane >> 4)*8);
    const u32 b_kk  = (u32)(((lane >> 3) & 1)*8);
    const u32 aBase = smem + SMA_OFF;
    const u32 bBase = smem + SMB_OFF;

    for (int gi = 0; gi < 4; gi++) {
        const int g = gq*4 + gi;
        __syncthreads();
        for (int i = tid; i < 64*32; i += 256) {
            int n = i >> 5, kq = i & 31;
            *(uint4*)&smB[n*APAD + kq*8] =
                *(const uint4*)&g_poolT[(size_t)(g*64 + n)*KPAD + kq*8];
        }
        if (tid < 128)
            smIv[tid] = g_minv[(size_t)(etile*128 + tid)*NGT + g];
        __syncthreads();

        float c[2][4][4];
        #pragma unroll
        for (int mf = 0; mf < 2; mf++)
            #pragma unroll
            for (int nf = 0; nf < 4; nf++)
                #pragma unroll
                for (int q = 0; q < 4; q++) c[mf][nf][q] = 0.f;

        #pragma unroll 4
        for (int ks = 0; ks < 16; ks++) {
            u32 a[2][4], b[4][2];
            #pragma unroll
            for (int mf = 0; mf < 2; mf++) {
                u32 ad = aBase + ((a_row + mf*16)*APAD + ks*16 + a_kk)*2;
                LDSM_X4(a[mf][0], a[mf][1], a[mf][2], a[mf][3], ad);
            }
            #pragma unroll
            for (int nh = 0; nh < 2; nh++) {
                u32 bd = bBase + ((b_row + nh*16)*APAD + ks*16 + b_kk)*2;
                LDSM_X4(b[nh*2][0], b[nh*2][1], b[nh*2+1][0], b[nh*2+1][1], bd);
            }
            #pragma unroll
            for (int mf = 0; mf < 2; mf++)
                #pragma unroll
                for (int nf = 0; nf < 4; nf++)
                    MMA_BF16(c[mf][nf][0], c[mf][nf][1], c[mf][nf][2], c[mf][nf][3],
                             a[mf][0], a[mf][1], a[mf][2], a[mf][3],
                             b[nf][0], b[nf][1]);
        }

        #pragma unroll
        for (int mf = 0; mf < 2; mf++) {
            int mLoc = wm*32 + mf*16 + (lane >> 2);
            int eLo = etile*128 + mLoc;
            int eHi = eLo + 8;
            float ivLo = smIv[mLoc], ivHi = smIv[mLoc + 8];
            #pragma unroll
            for (int nf = 0; nf < 4; nf++) {
                int d = wn*32 + nf*8 + (lane & 3)*2;
                if (eLo < NED) {
                    float2 v; v.x = c[mf][nf][0]*ivLo; v.y = c[mf][nf][1]*ivLo;
                    *(float2*)&g_gt[(size_t)eLo*GTS + g*64 + d] = v;
                }
                if (eHi < NED) {
                    float2 v; v.x = c[mf][nf][2]*ivHi; v.y = c[mf][nf][3]*ivHi;
                    *(float2*)&g_gt[(size_t)eHi*GTS + g*64 + d] = v;
                }
            }
        }
    }
}

/* ========= kernel 4: per-edge mean / unbiased std (single pass) ========= */
__global__ void __launch_bounds__(256, 4)
stats_kernel(float* __restrict__ out)
{
    __shared__ float red1[256], red2[256], redc[256];
    const int e = blockIdx.x, tid = threadIdx.x;
    const int d = tid & 63, part = tid >> 6;
    const float* gt = g_gt + (size_t)e*GTS;

    float s1 = 0.f, s2 = 0.f, cnt = 0.f;
    for (int gg = part*128; gg < part*128 + 128; gg++) {
        float x = gt[gg*DD + d];
        s1 += x;
        s2 = fmaf(x, x, s2);
        cnt += (g_minv[(size_t)e*NGT + gg] > 0.f) ? 1.f : 0.f;
    }
    red1[tid] = s1; red2[tid] = s2; redc[tid] = cnt;
    __syncthreads();
    if (tid < 64) {
        float nv = redc[d] + redc[64+d] + redc[128+d] + redc[192+d];
        float t1 = red1[d] + red1[64+d] + red1[128+d] + red1[192+d];
        float t2 = red2[d] + red2[64+d] + red2[128+d] + red2[192+d];
        float mn = t1 / fmaxf(nv, 1.f);
        float var = (t2 - nv*mn*mn) / fmaxf(nv - 1.f, 1.f);
        var = fmaxf(var, 0.f);
        out[(size_t)e*2*DD + d]      = mn;
        out[(size_t)e*2*DD + DD + d] = (nv > 1.f) ? sqrtf(var) : 0.f;
    }
}

/* ------------------------------ host -------------------------------------*/
extern "C" void kernel_launch(void* const* d_in, const int* in_sizes, int n_in,
                              void* d_out, int out_size)
{
    int o = (n_in > 5 && in_sizes[5] == (NSP+1)*DD) ? 0 : 1;

    const int* edge = (const int*)d_in[0];
    const int* sp   = (const int*)d_in[1];
    const u8*  leaf = (const u8*)d_in[2];
    const u8*  clad = (const u8*)d_in[4];
    const float* emb = (const float*)d_in[5+o];
    const float* W1  = (const float*)d_in[6+o];
    const float* b1  = (const float*)d_in[7+o];
    const float* W2  = (const float*)d_in[8+o];
    const float* b2  = (const float*)d_in[9+o];
    const float* eps = (const float*)d_in[10+o];
    const float* gam = (const float*)d_in[11+o];
    const float* bet = (const float*)d_in[12+o];

    cudaFuncSetAttribute(gin_kernel,      cudaFuncAttributeMaxDynamicSharedMemorySize, GIN_SMEM);
    cudaFuncSetAttribute(gemm_mma_kernel, cudaFuncAttributeMaxDynamicSharedMemorySize, SMG_TOT);

    gin_kernel<<<NGT, NT, GIN_SMEM>>>(edge, sp, leaf, emb, W1, b1, W2, b2, eps, gam, bet);
    maskprep_kernel<<<EPAD, KPAD>>>(clad, leaf);
    transpose_kernel<<<dim3(GTS/32, KPAD/32), 256>>>();
    cnt_kernel<<<dim3(NED, 2), 256>>>(clad, leaf);
    gemm_mma_kernel<<<dim3(128, 4), 256, SMG_TOT>>>();
    stats_kernel<<<NED, 256>>>((float*)d_out);
    (void)out_size; (void)n_in;
}

// round 16
// speedup vs baseline: 1.1146x; 1.0504x over previous
#include <cuda_runtime.h>
#include <cuda_bf16.h>
#include <cuda_fp16.h>
#include <cstdint>

#define NGT 512
#define NN  399
#define NSP 200
#define NED 397
#define DD  64
#define EPT 398
#define ECOLS (NGT*EPT*2)
#define RS  65
#define HS  72                 /* fp16 row stride (conflict-free ldmatrix) */
#define GTS (NGT*DD)
#define KPAD 208               /* 13 k-steps of 16 (>= 200 species) */
#define KQ4  26                /* KPAD/8 */
#define EPAD 512
#define NT  800                /* 25 warps: one 16-row chunk per warp */

/* gin smem layout (bytes) */
#define GIN_HOFF 113456
#define GIN_WOFF 171056
#define GIN_SMEM 180272

typedef unsigned char u8;
typedef unsigned long long ull;
typedef unsigned int u32;
typedef unsigned short u16;

/* ---------------- scratch (static device globals) ----------------------- */
__device__ __nv_bfloat16 g_poolT[(size_t)GTS*KPAD];       /* [gd][s] */
__device__ __nv_bfloat16 g_validT[(size_t)NGT*KPAD];      /* [g][s]  */
__device__ __nv_bfloat16 g_maskA[(size_t)EPAD*KPAD];      /* [e][s]  */
__device__ float g_gt[(size_t)400*GTS];                   /* [e][g][d] 52MB */
__device__ float g_minv[(size_t)EPAD*NGT];                /* [e][g] */

__device__ __forceinline__ u32 smem_u32(const void* p){
    u32 a; asm("{ .reg .u64 t; cvta.to.shared.u64 t, %1; cvt.u32.u64 %0, t; }" : "=r"(a) : "l"(p));
    return a;
}
#define LDSM_X4(r0,r1,r2,r3,addr) \
    asm volatile("ldmatrix.sync.aligned.m8n8.x4.shared.b16 {%0,%1,%2,%3}, [%4];" \
        : "=r"(r0), "=r"(r1), "=r"(r2), "=r"(r3) : "r"(addr))
#define LDSM_X4_T(r0,r1,r2,r3,addr) \
    asm volatile("ldmatrix.sync.aligned.m8n8.x4.trans.shared.b16 {%0,%1,%2,%3}, [%4];" \
        : "=r"(r0), "=r"(r1), "=r"(r2), "=r"(r3) : "r"(addr))
#define MMA_BF16(c0,c1,c2,c3,a0,a1,a2,a3,b0,b1) \
    asm volatile("mma.sync.aligned.m16n8k16.row.col.f32.bf16.bf16.f32 " \
        "{%0,%1,%2,%3},{%4,%5,%6,%7},{%8,%9},{%0,%1,%2,%3};" \
        : "+f"(c0), "+f"(c1), "+f"(c2), "+f"(c3) \
        : "r"(a0), "r"(a1), "r"(a2), "r"(a3), "r"(b0), "r"(b1))
#define MMA_F16(c0,c1,c2,c3,a0,a1,a2,a3,b0,b1) \
    asm volatile("mma.sync.aligned.m16n8k16.row.col.f32.f16.f16.f32 " \
        "{%0,%1,%2,%3},{%4,%5,%6,%7},{%8,%9},{%0,%1,%2,%3};" \
        : "+f"(c0), "+f"(c1), "+f"(c2), "+f"(c3) \
        : "r"(a0), "r"(a1), "r"(a2), "r"(a3), "r"(b0), "r"(b1))

/* ======================= kernel 1: GIN per tree ========================== */
__global__ void __launch_bounds__(NT, 1)
gin_kernel(const int* __restrict__ edge, const int* __restrict__ sp,
           const u8* __restrict__ leaf, const float* __restrict__ emb,
           const float* __restrict__ W1, const float* __restrict__ b1,
           const float* __restrict__ W2, const float* __restrict__ b2,
           const float* __restrict__ eps, const float* __restrict__ gam,
           const float* __restrict__ bet)
{
    extern __shared__ float smf[];
    float* xb   = smf;
    float* vec  = smf + 26000;
    int*   ipar = (int*)(smf + 26256);
    int*   ioff = ipar + 400;
    int*   ilist= ioff + 401;
    int*   soff = ilist + 400;
    int*   slist= soff + 204;
    short* ssp  = (short*)(slist + 400);
    u8*    slf  = (u8*)(ssp + 400);
    __half* hbf = (__half*)((char*)smf + GIN_HOFF);
    __half* wbf = (__half*)((char*)smf + GIN_WOFF);

    const int tid = threadIdx.x;
    const int g   = blockIdx.x;
    const int lane = tid & 31, wrp = tid >> 5;
    const int em  = (edge[1] == 0) ? 2 : 1;
    const int smu = (sp[1]   == 0) ? 2 : 1;
    const int bw  = leaf[1] ? 1 : (leaf[4] ? 4 : 8);

    for (int n = tid; n < NN; n += NT) {
        size_t gi = (size_t)g*NN + n;
        int s = sp[(size_t)smu * gi];
        ssp[n] = (short)s;
        slf[n] = (s >= 0 && leaf[gi * (size_t)bw] != 0) ? 1 : 0;
    }
    for (int n = tid; n <= NN;  n += NT) ioff[n] = 0;
    for (int s = tid; s <= NSP; s += NT) soff[s] = 0;
    __syncthreads();

    for (int i = tid; i < NN*DD; i += NT) {
        int n = i >> 6, d = i & 63;
        int s = ssp[n];
        xb[n*RS + d] = emb[(s < 0 ? NSP : s)*DD + d];
    }
    for (int e = tid; e < EPT; e += NT) {
        int p = edge[(size_t)em * ((size_t)ECOLS + (size_t)g*EPT + e)] - g*NN;
        ipar[e+1] = p;
        atomicAdd(&ioff[p], 1);
    }
    if (tid == 0) ipar[0] = 0;
    for (int n = tid; n < NN; n += NT)
        if (slf[n]) atomicAdd(&soff[ssp[n]], 1);
    __syncthreads();

    /* exclusive scans */
    if (wrp == 0) {
        int carry = 0;
        for (int base = 0; base < NN; base += 32) {
            int idx = base + lane;
            int orig = (idx < NN) ? ioff[idx] : 0;
            int v = orig;
            #pragma unroll
            for (int o = 1; o < 32; o <<= 1) { int t = __shfl_up_sync(0xffffffffu, v, o); if (lane >= o) v += t; }
            if (idx < NN) ioff[idx] = carry + v - orig;
            carry += __shfl_sync(0xffffffffu, v, 31);
        }
        if (lane == 0) ioff[NN] = carry;
    } else if (wrp == 1) {
        int carry = 0;
        for (int base = 0; base < NSP; base += 32) {
            int idx = base + lane;
            int orig = (idx < NSP) ? soff[idx] : 0;
            int v = orig;
            #pragma unroll
            for (int o = 1; o < 32; o <<= 1) { int t = __shfl_up_sync(0xffffffffu, v, o); if (lane >= o) v += t; }
            if (idx < NSP) soff[idx] = carry + v - orig;
            carry += __shfl_sync(0xffffffffu, v, 31);
        }
        if (lane == 0) soff[NSP] = carry;
    }
    __syncthreads();

    /* deterministic CSR fill via rank counting */
    for (int c = 1 + tid; c < NN; c += NT) {
        int p = ipar[c], r = 0;
        for (int c2 = 1; c2 < c; c2++) r += (ipar[c2] == p);
        ilist[ioff[p] + r] = c;
    }
    for (int n = tid; n < NN; n += NT) {
        if (slf[n]) {
            int s = ssp[n], r = 0;
            for (int n2 = 0; n2 < n; n2++) r += (slf[n2] && ssp[n2] == s);
            slist[soff[s] + r] = n;
        }
    }
    __syncthreads();

    const u32 hbf_u = smem_u32(hbf);
    const u32 wbf_u = smem_u32(wbf);
    const u32 a_row = (u32)((lane & 7) + ((lane >> 3) & 1)*8);
    const u32 a_kk  = (u32)((lane >> 4)*8);
    const u32 w_row = (u32)((lane & 7) + ((lane >> 3) & 1)*8);
    const u32 w_col = (u32)((lane >> 4)*8);

    for (int l = 0; l < 2; l++) {
        const float* W1l = W1 + l*DD*DD;
        const float* W2l = W2 + l*DD*DD;
        if (tid < 64) {
            vec[tid]       = b1[l*DD + tid];
            vec[64 + tid]  = b2[l*DD + tid];
            vec[128 + tid] = gam[l*DD + tid];
            vec[192 + tid] = bet[l*DD + tid];
        }
        for (int i = tid; i < DD*DD; i += NT)
            wbf[(i >> 6)*HS + (i & 63)] = __float2half_rn(W1l[i]);
        const float e1 = 1.f + eps[l];
        __syncthreads();

        for (int i = tid; i < NN*DD; i += NT) {
            int n = i >> 6, d = i & 63;
            float a = e1 * xb[n*RS + d];
            if (n > 0) a += xb[ipar[n]*RS + d];
            int o1 = ioff[n+1];
            for (int j = ioff[n]; j < o1; j++) a += xb[ilist[j]*RS + d];
            hbf[n*HS + d] = __float2half_rn(a);
        }
        __syncthreads();

        for (int c0 = wrp; c0 < 25; c0 += 25) {
            int m0 = c0*16;
            float acc[8][4];
            #pragma unroll
            for (int nt = 0; nt < 8; nt++)
                #pragma unroll
                for (int q = 0; q < 4; q++) acc[nt][q] = 0.f;
            #pragma unroll
            for (int ks = 0; ks < 4; ks++) {
                u32 a0,a1,a2,a3;
                LDSM_X4(a0,a1,a2,a3, hbf_u + (((u32)m0 + a_row)*HS + (u32)ks*16 + a_kk)*2);
                u32 b[8][2];
                #pragma unroll
                for (int np = 0; np < 4; np++)
                    LDSM_X4_T(b[np*2][0], b[np*2][1], b[np*2+1][0], b[np*2+1][1],
                              wbf_u + (((u32)ks*16 + w_row)*HS + (u32)np*16 + w_col)*2);
                #pragma unroll
                for (int nt = 0; nt < 8; nt++)
                    MMA_F16(acc[nt][0],acc[nt][1],acc[nt][2],acc[nt][3],
                            a0,a1,a2,a3, b[nt][0],b[nt][1]);
            }
            int r0 = m0 + (lane >> 2), r1 = r0 + 8;
            #pragma unroll
            for (int nt = 0; nt < 8; nt++) {
                int col = nt*8 + (lane & 3)*2;
                float bb0 = vec[col], bb1 = vec[col+1];
                *(__half2*)&hbf[r0*HS + col] = __floats2half2_rn(
                    fmaxf(acc[nt][0] + bb0, 0.f), fmaxf(acc[nt][1] + bb1, 0.f));
                *(__half2*)&hbf[r1*HS + col] = __floats2half2_rn(
                    fmaxf(acc[nt][2] + bb0, 0.f), fmaxf(acc[nt][3] + bb1, 0.f));
            }
        }
        __syncthreads();

        for (int i = tid; i < DD*DD; i += NT)
            wbf[(i >> 6)*HS + (i & 63)] = __float2half_rn(W2l[i]);
        __syncthreads();

        for (int c0 = wrp; c0 < 25; c0 += 25) {
            int m0 = c0*16;
            float acc[8][4];
            #pragma unroll
            for (int nt = 0; nt < 8; nt++)
                #pragma unroll
                for (int q = 0; q < 4; q++) acc[nt][q] = 0.f;
            #pragma unroll
            for (int ks = 0; ks < 4; ks++) {
                u32 a0,a1,a2,a3;
                LDSM_X4(a0,a1,a2,a3, hbf_u + (((u32)m0 + a_row)*HS + (u32)ks*16 + a_kk)*2);
                u32 b[8][2];
                #pragma unroll
                for (int np = 0; np < 4; np++)
                    LDSM_X4_T(b[np*2][0], b[np*2][1], b[np*2+1][0], b[np*2+1][1],
                              wbf_u + (((u32)ks*16 + w_row)*HS + (u32)np*16 + w_col)*2);
                #pragma unroll
                for (int nt = 0; nt < 8; nt++)
                    MMA_F16(acc[nt][0],acc[nt][1],acc[nt][2],acc[nt][3],
                            a0,a1,a2,a3, b[nt][0],b[nt][1]);
            }
            int r0 = m0 + (lane >> 2), r1 = r0 + 8;
            float y0[16], y1[16];
            #pragma unroll
            for (int nt = 0; nt < 8; nt++) {
                int col = nt*8 + (lane & 3)*2;
                float b20 = vec[64+col], b21 = vec[64+col+1];
                y0[2*nt]   = acc[nt][0] + b20 + xb[r0*RS + col];
                y0[2*nt+1] = acc[nt][1] + b21 + xb[r0*RS + col+1];
                y1[2*nt]   = acc[nt][2] + b20 + xb[r1*RS + col];
                y1[2*nt+1] = acc[nt][3] + b21 + xb[r1*RS + col+1];
            }
            float s0 = 0.f, s1 = 0.f;
            #pragma unroll
            for (int q = 0; q < 16; q++) { s0 += y0[q]; s1 += y1[q]; }
            s0 += __shfl_xor_sync(0xffffffffu, s0, 1);
            s0 += __shfl_xor_sync(0xffffffffu, s0, 2);
            s1 += __shfl_xor_sync(0xffffffffu, s1, 1);
            s1 += __shfl_xor_sync(0xffffffffu, s1, 2);
            float mu0 = s0*(1.f/DD), mu1 = s1*(1.f/DD);
            float v0 = 0.f, v1 = 0.f;
            #pragma unroll
            for (int q = 0; q < 16; q++) {
                float d0 = y0[q]-mu0, d1 = y1[q]-mu1;
                v0 = fmaf(d0,d0,v0); v1 = fmaf(d1,d1,v1);
            }
            v0 += __shfl_xor_sync(0xffffffffu, v0, 1);
            v0 += __shfl_xor_sync(0xffffffffu, v0, 2);
            v1 += __shfl_xor_sync(0xffffffffu, v1, 1);
            v1 += __shfl_xor_sync(0xffffffffu, v1, 2);
            float rs0 = rsqrtf(v0*(1.f/DD) + 1e-5f);
            float rs1 = rsqrtf(v1*(1.f/DD) + 1e-5f);
            #pragma unroll
            for (int nt = 0; nt < 8; nt++) {
                int col = nt*8 + (lane & 3)*2;
                xb[r0*RS + col]   = (y0[2*nt]  -mu0)*rs0*vec[128+col]   + vec[192+col];
                xb[r0*RS + col+1] = (y0[2*nt+1]-mu0)*rs0*vec[128+col+1] + vec[192+col+1];
                xb[r1*RS + col]   = (y1[2*nt]  -mu1)*rs1*vec[128+col]   + vec[192+col];
                xb[r1*RS + col+1] = (y1[2*nt+1]-mu1)*rs1*vec[128+col+1] + vec[192+col+1];
            }
        }
        __syncthreads();
    }

    /* species pooling -> poolT bf16 direct (s-chunked) + validT row */
    for (int i = tid; i < DD*KQ4; i += NT) {
        int d = i / KQ4, sc = (i % KQ4) * 8;
        u16 v[8];
        #pragma unroll
        for (int j = 0; j < 8; j++) {
            int s = sc + j;
            float a = 0.f; int cnt = 0;
            if (s < NSP) {
                int o0 = soff[s], o1 = soff[s+1];
                cnt = o1 - o0;
                for (int jj = o0; jj < o1; jj++) a += xb[slist[jj]*RS + d];
            }
            __nv_bfloat16 b = __float2bfloat16((cnt > 0) ? (a / (float)cnt) : 0.f);
            v[j] = *(u16*)&b;
        }
        *(uint4*)&g_poolT[(size_t)(g*DD + d)*KPAD + sc] = *(uint4*)v;
    }
    for (int s = tid; s < KPAD; s += NT) {
        float v = (s < NSP && soff[s+1] > soff[s]) ? 1.f : 0.f;
        __nv_bfloat16 b = __float2bfloat16(v);
        *(u16*)&g_validT[(size_t)g*KPAD + s] = *(u16*)&b;
    }
}

/* =============== kernel 2b: build bf16 mask A [EPAD x KPAD] ============= */
__global__ void maskprep_kernel(const u8* __restrict__ clade, const u8* __restrict__ leaf)
{
    const int e = blockIdx.x, s = threadIdx.x;   /* grid EPAD, block KPAD */
    const int bw = leaf[1] ? 1 : (leaf[4] ? 4 : 8);
    float v = 0.f;
    if (e < NED && s < NSP && clade[((size_t)e*NSP + s)*(size_t)bw]) v = 1.f;
    g_maskA[(size_t)e*KPAD + s] = __float2bfloat16(v);
}

/* ====== kernel 2e: ccnt GEMM -> minv  (exact bf16 0/1 x 0/1 MMA) ======== */
#define APAD 216
#define SMCB_OFF (128*APAD*2)
#define SMC_TOT  (2*128*APAD*2)            /* 110592 */

__global__ void __launch_bounds__(256, 1)
cntmma_kernel()
{
    extern __shared__ char smcc[];
    const u32 smem = smem_u32(smcc);
    __nv_bfloat16* smA = (__nv_bfloat16*)(smcc);
    __nv_bfloat16* smB = (__nv_bfloat16*)(smcc + SMCB_OFF);

    const int tid  = threadIdx.x;
    const int lane = tid & 31, wrp = tid >> 5;
    const int wm   = wrp >> 1, wn = wrp & 1;   /* warp tile 32e x 64g */
    const int gtile = blockIdx.x;              /* 4 tiles of 128 g */
    const int etile = blockIdx.y;              /* 4 tiles of 128 e */

    for (int i = tid; i < 128*KQ4; i += 256) {
        int m = i / KQ4, kq = i % KQ4;
        *(uint4*)&smA[m*APAD + kq*8] =
            *(const uint4*)&g_maskA[(size_t)(etile*128 + m)*KPAD + kq*8];
        *(uint4*)&smB[m*APAD + kq*8] =
            *(const uint4*)&g_validT[(size_t)(gtile*128 + m)*KPAD + kq*8];
    }
    __syncthreads();

    const u32 a_row = (u32)(wm*32 + (lane & 7) + ((lane >> 3) & 1)*8);
    const u32 a_kk  = (u32)((lane >> 4)*8);
    const u32 b_row = (u32)(wn*64 + (lane & 7) + (lane >> 4)*8);
    const u32 b_kk  = (u32)(((lane >> 3) & 1)*8);
    const u32 aBase = smem;
    const u32 bBase = smem + SMCB_OFF;

    float c[2][8][4];
    #pragma unroll
    for (int mf = 0; mf < 2; mf++)
        #pragma unroll
        for (int nf = 0; nf < 8; nf++)
            #pragma unroll
            for (int q = 0; q < 4; q++) c[mf][nf][q] = 0.f;

    for (int ks = 0; ks < 13; ks++) {
        u32 a[2][4], b[8][2];
        #pragma unroll
        for (int mf = 0; mf < 2; mf++) {
            u32 ad = aBase + ((a_row + mf*16)*APAD + ks*16 + a_kk)*2;
            LDSM_X4(a[mf][0], a[mf][1], a[mf][2], a[mf][3], ad);
        }
        #pragma unroll
        for (int nh = 0; nh < 4; nh++) {
            u32 bd = bBase + ((b_row + nh*16)*APAD + ks*16 + b_kk)*2;
            LDSM_X4(b[nh*2][0], b[nh*2][1], b[nh*2+1][0], b[nh*2+1][1], bd);
        }
        #pragma unroll
        for (int mf = 0; mf < 2; mf++)
            #pragma unroll
            for (int nf = 0; nf < 8; nf++)
                MMA_BF16(c[mf][nf][0], c[mf][nf][1], c[mf][nf][2], c[mf][nf][3],
                         a[mf][0], a[mf][1], a[mf][2], a[mf][3],
                         b[nf][0], b[nf][1]);
    }

    #pragma unroll
    for (int mf = 0; mf < 2; mf++) {
        int eLo = etile*128 + wm*32 + mf*16 + (lane >> 2);
        int eHi = eLo + 8;
        #pragma unroll
        for (int nf = 0; nf < 8; nf++) {
            int gg = gtile*128 + wn*64 + nf*8 + (lane & 3)*2;
            if (eLo < NED) {
                float2 v;
                v.x = (c[mf][nf][0] > 0.f) ? (1.f/c[mf][nf][0]) : 0.f;
                v.y = (c[mf][nf][1] > 0.f) ? (1.f/c[mf][nf][1]) : 0.f;
                *(float2*)&g_minv[(size_t)eLo*NGT + gg] = v;
            }
            if (eHi < NED) {
                float2 v;
                v.x = (c[mf][nf][2] > 0.f) ? (1.f/c[mf][nf][2]) : 0.f;
                v.y = (c[mf][nf][3] > 0.f) ? (1.f/c[mf][nf][3]) : 0.f;
                *(float2*)&g_minv[(size_t)eHi*NGT + gg] = v;
            }
        }
    }
}

/* ====== kernel 3: mma.sync bf16 GEMM  C[e,gd] = sum_s M[e,s] P[gd,s] ==== */
#define SMA_OFF 0
#define SMB_OFF (128*APAD*2)               /* 55296 */
#define SMIV_OFF (SMB_OFF + 64*APAD*2)     /* 82944 */
#define SMG_TOT (SMIV_OFF + 128*4)         /* 83456 */

__global__ void __launch_bounds__(256, 1)
gemm_mma_kernel()
{
    extern __shared__ char smg[];
    const u32 smem = smem_u32(smg);
    __nv_bfloat16* smA = (__nv_bfloat16*)(smg + SMA_OFF);
    __nv_bfloat16* smB = (__nv_bfloat16*)(smg + SMB_OFF);
    float*         smIv= (float*)(smg + SMIV_OFF);

    const int tid  = threadIdx.x;
    const int lane = tid & 31, wrp = tid >> 5;
    const int wm   = wrp >> 1, wn = wrp & 1;
    const int gq    = blockIdx.x;
    const int etile = blockIdx.y;

    for (int i = tid; i < 128*KQ4; i += 256) {
        int m = i / KQ4, kq = i % KQ4;
        *(uint4*)&smA[m*APAD + kq*8] =
            *(const uint4*)&g_maskA[(size_t)(etile*128 + m)*KPAD + kq*8];
    }

    const u32 a_row = (u32)(wm*32 + (lane & 7) + ((lane >> 3) & 1)*8);
    const u32 a_kk  = (u32)((lane >> 4)*8);
    const u32 b_row = (u32)(wn*32 + (lane & 7) + (lane >> 4)*8);
    const u32 b_kk  = (u32)(((lane >> 3) & 1)*8);
    const u32 aBase = smem + SMA_OFF;
    const u32 bBase = smem + SMB_OFF;

    for (int gi = 0; gi < 4; gi++) {
        const int g = gq*4 + gi;
        __syncthreads();
        for (int i = tid; i < 64*KQ4; i += 256) {
            int n = i / KQ4, kq = i % KQ4;
            *(uint4*)&smB[n*APAD + kq*8] =
                *(const uint4*)&g_poolT[(size_t)(g*64 + n)*KPAD + kq*8];
        }
        if (tid < 128)
            smIv[tid] = g_minv[(size_t)(etile*128 + tid)*NGT + g];
        __syncthreads();

        float c[2][4][4];
        #pragma unroll
        for (int mf = 0; mf < 2; mf++)
            #pragma unroll
            for (int nf = 0; nf < 4; nf++)
                #pragma unroll
                for (int q = 0; q < 4; q++) c[mf][nf][q] = 0.f;

        #pragma unroll 4
        for (int ks = 0; ks < 13; ks++) {
            u32 a[2][4], b[4][2];
            #pragma unroll
            for (int mf = 0; mf < 2; mf++) {
                u32 ad = aBase + ((a_row + mf*16)*APAD + ks*16 + a_kk)*2;
                LDSM_X4(a[mf][0], a[mf][1], a[mf][2], a[mf][3], ad);
            }
            #pragma unroll
            for (int nh = 0; nh < 2; nh++) {
                u32 bd = bBase + ((b_row + nh*16)*APAD + ks*16 + b_kk)*2;
                LDSM_X4(b[nh*2][0], b[nh*2][1], b[nh*2+1][0], b[nh*2+1][1], bd);
            }
            #pragma unroll
            for (int mf = 0; mf < 2; mf++)
                #pragma unroll
                for (int nf = 0; nf < 4; nf++)
                    MMA_BF16(c[mf][nf][0], c[mf][nf][1], c[mf][nf][2], c[mf][nf][3],
                             a[mf][0], a[mf][1], a[mf][2], a[mf][3],
                             b[nf][0], b[nf][1]);
        }

        #pragma unroll
        for (int mf = 0; mf < 2; mf++) {
            int mLoc = wm*32 + mf*16 + (lane >> 2);
            int eLo = etile*128 + mLoc;
            int eHi = eLo + 8;
            float ivLo = smIv[mLoc], ivHi = smIv[mLoc + 8];
            #pragma unroll
            for (int nf = 0; nf < 4; nf++) {
                int d = wn*32 + nf*8 + (lane & 3)*2;
                if (eLo < NED) {
                    float2 v; v.x = c[mf][nf][0]*ivLo; v.y = c[mf][nf][1]*ivLo;
                    *(float2*)&g_gt[(size_t)eLo*GTS + g*64 + d] = v;
                }
                if (eHi < NED) {
                    float2 v; v.x = c[mf][nf][2]*ivHi; v.y = c[mf][nf][3]*ivHi;
                    *(float2*)&g_gt[(size_t)eHi*GTS + g*64 + d] = v;
                }
            }
        }
    }
}

/* ========= kernel 4: per-edge mean / unbiased std (single pass) ========= */
__global__ void __launch_bounds__(256, 4)
stats_kernel(float* __restrict__ out)
{
    __shared__ float red1[256], red2[256], redc[256];
    const int e = blockIdx.x, tid = threadIdx.x;
    const int d = tid & 63, part = tid >> 6;
    const float* gt = g_gt + (size_t)e*GTS;

    float s1 = 0.f, s2 = 0.f, cnt = 0.f;
    for (int gg = part*128; gg < part*128 + 128; gg++) {
        float x = gt[gg*DD + d];
        s1 += x;
        s2 = fmaf(x, x, s2);
        cnt += (g_minv[(size_t)e*NGT + gg] > 0.f) ? 1.f : 0.f;
    }
    red1[tid] = s1; red2[tid] = s2; redc[tid] = cnt;
    __syncthreads();
    if (tid < 64) {
        float nv = redc[d] + redc[64+d] + redc[128+d] + redc[192+d];
        float t1 = red1[d] + red1[64+d] + red1[128+d] + red1[192+d];
        float t2 = red2[d] + red2[64+d] + red2[128+d] + red2[192+d];
        float mn = t1 / fmaxf(nv, 1.f);
        float var = (t2 - nv*mn*mn) / fmaxf(nv - 1.f, 1.f);
        var = fmaxf(var, 0.f);
        out[(size_t)e*2*DD + d]      = mn;
        out[(size_t)e*2*DD + DD + d] = (nv > 1.f) ? sqrtf(var) : 0.f;
    }
}

/* ------------------------------ host -------------------------------------*/
extern "C" void kernel_launch(void* const* d_in, const int* in_sizes, int n_in,
                              void* d_out, int out_size)
{
    int o = (n_in > 5 && in_sizes[5] == (NSP+1)*DD) ? 0 : 1;

    const int* edge = (const int*)d_in[0];
    const int* sp   = (const int*)d_in[1];
    const u8*  leaf = (const u8*)d_in[2];
    const u8*  clad = (const u8*)d_in[4];
    const float* emb = (const float*)d_in[5+o];
    const float* W1  = (const float*)d_in[6+o];
    const float* b1  = (const float*)d_in[7+o];
    const float* W2  = (const float*)d_in[8+o];
    const float* b2  = (const float*)d_in[9+o];
    const float* eps = (const float*)d_in[10+o];
    const float* gam = (const float*)d_in[11+o];
    const float* bet = (const float*)d_in[12+o];

    cudaFuncSetAttribute(gin_kernel,      cudaFuncAttributeMaxDynamicSharedMemorySize, GIN_SMEM);
    cudaFuncSetAttribute(gemm_mma_kernel, cudaFuncAttributeMaxDynamicSharedMemorySize, SMG_TOT);
    cudaFuncSetAttribute(cntmma_kernel,   cudaFuncAttributeMaxDynamicSharedMemorySize, SMC_TOT);

    gin_kernel<<<NGT, NT, GIN_SMEM>>>(edge, sp, leaf, emb, W1, b1, W2, b2, eps, gam, bet);
    maskprep_kernel<<<EPAD, KPAD>>>(clad, leaf);
    cntmma_kernel<<<dim3(4, 4), 256, SMC_TOT>>>();
    gemm_mma_kernel<<<dim3(128, 4), 256, SMG_TOT>>>();
    stats_kernel<<<NED, 256>>>((float*)d_out);
    (void)out_size; (void)n_in;
}